// round 16
// baseline (speedup 1.0000x reference)
#include <cuda_runtime.h>
#include <cstdint>

#define NBLOCKS     148
#define THREADS     256
#define CHUNK_ROWS  512
#define ROW_BYTES   40
#define CHUNK_BYTES (CHUNK_ROWS * ROW_BYTES)   /* 20480 per array */
#define STAGE_BYTES (2 * CHUNK_BYTES)          /* 40960: o + l     */
#define STAGES      5
#define SMEM_DATA   (STAGES * STAGE_BYTES)     /* 204800 bytes     */

__device__ double g_partials[NBLOCKS];
__device__ unsigned int g_count;

__device__ __forceinline__ uint32_t smem_u32(const void* p) {
    uint32_t a;
    asm("{ .reg .u64 t; cvta.to.shared.u64 t, %1; cvt.u32.u64 %0, t; }"
        : "=r"(a) : "l"(p));
    return a;
}

__device__ __forceinline__ void mbar_init(uint32_t mbar, uint32_t count) {
    asm volatile("mbarrier.init.shared.b64 [%0], %1;" :: "r"(mbar), "r"(count) : "memory");
}
__device__ __forceinline__ void mbar_expect_tx(uint32_t mbar, uint32_t bytes) {
    asm volatile("mbarrier.arrive.expect_tx.shared.b64 _, [%0], %1;"
                 :: "r"(mbar), "r"(bytes) : "memory");
}
__device__ __forceinline__ void mbar_wait_parity(uint32_t mbar, uint32_t parity) {
    uint32_t done;
    asm volatile(
        "{\n\t"
        ".reg .pred p;\n\t"
        "mbarrier.try_wait.parity.acquire.cta.shared::cta.b64 p, [%1], %2;\n\t"
        "selp.b32 %0, 1, 0, p;\n\t"
        "}" : "=r"(done) : "r"(mbar), "r"(parity) : "memory");
    if (!done) {
        asm volatile(
            "{\n\t"
            ".reg .pred P1;\n\t"
            "WL_%=:\n\t"
            "mbarrier.try_wait.parity.acquire.cta.shared::cta.b64 P1, [%0], %1, 0x989680;\n\t"
            "@P1 bra.uni WD_%=;\n\t"
            "bra.uni WL_%=;\n\t"
            "WD_%=:\n\t"
            "}" :: "r"(mbar), "r"(parity) : "memory");
    }
}
__device__ __forceinline__ void bulk_g2s(uint32_t dst, const void* src,
                                         uint32_t bytes, uint32_t mbar) {
    asm volatile(
        "cp.async.bulk.shared::cta.global.mbarrier::complete_tx::bytes [%0], [%1], %2, [%3];"
        :: "r"(dst), "l"(src), "r"(bytes), "r"(mbar) : "memory");
}

__global__ void __launch_bounds__(THREADS)
mse_tma_kernel(const float* __restrict__ o_g,
               const float* __restrict__ l_g,
               int n_rows, float* __restrict__ out) {
    extern __shared__ __align__(128) unsigned char smem[];
    __shared__ uint64_t mbar[STAGES];
    __shared__ float warp_sums[8];
    __shared__ bool is_last;

    const int tid = threadIdx.x;
    const uint32_t mbar0 = smem_u32(&mbar[0]);
    const uint32_t data0 = smem_u32(smem);

    if (tid == 0) {
        #pragma unroll
        for (int s = 0; s < STAGES; s++) mbar_init(mbar0 + s * 8, 1);
    }
    asm volatile("fence.proxy.async.shared::cta;" ::: "memory");
    __syncthreads();

    const int n_chunks = (n_rows + CHUNK_ROWS - 1) / CHUNK_ROWS;

    // Prologue: threads 0..STAGES-1 each issue one stage's loads in parallel
    // (per-stage mbarrier has a single owner, so ordering is unchanged).
    if (tid < STAGES) {
        const int it = tid;
        long long c = blockIdx.x + (long long)it * gridDim.x;
        if (c < n_chunks) {
            int rows = min(CHUNK_ROWS, (int)(n_rows - c * CHUNK_ROWS)) & ~1;
            uint32_t ob = (uint32_t)rows * ROW_BYTES;
            uint32_t mb = mbar0 + it * 8;
            uint32_t dst = data0 + it * STAGE_BYTES;
            const char* osrc = (const char*)o_g + c * (long long)CHUNK_BYTES;
            const char* lsrc = (const char*)l_g + c * (long long)CHUNK_BYTES;
            mbar_expect_tx(mb, 2 * ob);
            bulk_g2s(dst, osrc, ob, mb);
            bulk_g2s(dst + CHUNK_BYTES, lsrc, ob, mb);
        }
    }

    float acc = 0.0f;

    for (int it = 0;; it++) {
        long long c = blockIdx.x + (long long)it * gridDim.x;
        if (c >= n_chunks) break;
        const int s  = it % STAGES;
        const int ph = (it / STAGES) & 1;

        mbar_wait_parity(mbar0 + s * 8, (uint32_t)ph);

        const int rows  = min(CHUNK_ROWS, (int)(n_rows - c * CHUNK_ROWS)) & ~1;
        const int pairs = rows >> 1;

        if (tid < pairs) {
            // Two rows = 80B = 5 float4 per array. Warp LDS.128 request = 512B
            // = crossbar 4-phase floor; 80B lane stride adds no extra conflicts.
            const float4* o4 = (const float4*)(smem + s * STAGE_BYTES) + tid * 5;
            const float4* l4 = (const float4*)(smem + s * STAGE_BYTES + CHUNK_BYTES) + tid * 5;
            float4 ov0 = o4[0], ov1 = o4[1], ov2 = o4[2], ov3 = o4[3], ov4 = o4[4];
            float4 lv0 = l4[0], lv1 = l4[1], lv2 = l4[2], lv3 = l4[3], lv4 = l4[4];

            float o[20] = {ov0.x, ov0.y, ov0.z, ov0.w, ov1.x, ov1.y, ov1.z, ov1.w,
                           ov2.x, ov2.y, ov2.z, ov2.w, ov3.x, ov3.y, ov3.z, ov3.w,
                           ov4.x, ov4.y, ov4.z, ov4.w};
            float l[20] = {lv0.x, lv0.y, lv0.z, lv0.w, lv1.x, lv1.y, lv1.z, lv1.w,
                           lv2.x, lv2.y, lv2.z, lv2.w, lv3.x, lv3.y, lv3.z, lv3.w,
                           lv4.x, lv4.y, lv4.z, lv4.w};

            // COUNTS = {1,4,7,10} -> ncols = 1 + 3*cls
            int nc0 = 1 + 3 * __float2int_rn(l[0]);
            #pragma unroll
            for (int j = 0; j < 10; j++) {
                float d = o[j] - l[j];
                acc += (j < nc0) ? d * d : 0.0f;
            }
            int nc1 = 1 + 3 * __float2int_rn(l[10]);
            #pragma unroll
            for (int j = 0; j < 10; j++) {
                float d = o[10 + j] - l[10 + j];
                acc += (j < nc1) ? d * d : 0.0f;
            }
        }
        __syncthreads();  // all reads of stage s complete

        if (tid == 0) {
            int it2 = it + STAGES;
            long long c2 = blockIdx.x + (long long)it2 * gridDim.x;
            if (c2 < n_chunks) {
                int rows2 = min(CHUNK_ROWS, (int)(n_rows - c2 * CHUNK_ROWS)) & ~1;
                uint32_t ob = (uint32_t)rows2 * ROW_BYTES;
                uint32_t mb = mbar0 + s * 8;
                uint32_t dst = data0 + s * STAGE_BYTES;
                const char* osrc = (const char*)o_g + c2 * (long long)CHUNK_BYTES;
                const char* lsrc = (const char*)l_g + c2 * (long long)CHUNK_BYTES;
                mbar_expect_tx(mb, 2 * ob);
                bulk_g2s(dst, osrc, ob, mb);
                bulk_g2s(dst + CHUNK_BYTES, lsrc, ob, mb);
            }
        }
    }

    // Odd final row (n_rows odd): chunk path rounds rows down to even.
    if ((n_rows & 1) && blockIdx.x == 0 && tid == 0) {
        long long r = (long long)n_rows - 1;
        const float* orow = o_g + r * 10;
        const float* lrow = l_g + r * 10;
        int nc = 1 + 3 * __float2int_rn(lrow[0]);
        #pragma unroll
        for (int j = 0; j < 10; j++) {
            float d = orow[j] - lrow[j];
            acc += (j < nc) ? d * d : 0.0f;
        }
    }

    // Warp reduce
    #pragma unroll
    for (int off = 16; off > 0; off >>= 1)
        acc += __shfl_xor_sync(0xFFFFFFFFu, acc, off);

    int lane = tid & 31;
    int wid  = tid >> 5;
    if (lane == 0) warp_sums[wid] = acc;
    __syncthreads();

    if (wid == 0) {
        float v = (lane < 8) ? warp_sums[lane] : 0.0f;
        #pragma unroll
        for (int off = 4; off > 0; off >>= 1)
            v += __shfl_xor_sync(0xFFFFFFFFu, v, off);
        if (lane == 0) {
            g_partials[blockIdx.x] = (double)v;
            __threadfence();
            unsigned int ticket = atomicAdd(&g_count, 1u);
            is_last = (ticket == gridDim.x - 1);
        }
        __syncwarp();

        // Serial epilogue: single warp of the last block finalizes.
        if (is_last) {
            __threadfence();
            double dsum = 0.0;
            for (int i = lane; i < NBLOCKS; i += 32)
                dsum += g_partials[i];
            #pragma unroll
            for (int off = 16; off > 0; off >>= 1)
                dsum += __shfl_xor_sync(0xFFFFFFFFu, dsum, off);
            if (lane == 0) {
                out[0] = (float)(dsum / (double)n_rows);
                g_count = 0;  // reset for next graph replay
            }
        }
    }
}

extern "C" void kernel_launch(void* const* d_in, const int* in_sizes, int n_in,
                              void* d_out, int out_size) {
    const float* outputs = (const float*)d_in[0];
    const float* labels  = (const float*)d_in[1];
    float* out = (float*)d_out;

    int n_rows = in_sizes[0] / 10;

    cudaFuncSetAttribute(mse_tma_kernel,
                         cudaFuncAttributeMaxDynamicSharedMemorySize, SMEM_DATA);

    mse_tma_kernel<<<NBLOCKS, THREADS, SMEM_DATA>>>(outputs, labels, n_rows, out);
}

// round 17
// speedup vs baseline: 1.0396x; 1.0396x over previous
#include <cuda_runtime.h>
#include <cstdint>

#define NBLOCKS     148
#define THREADS     256
#define CHUNK_ROWS  512
#define ROW_BYTES   40
#define CHUNK_BYTES (CHUNK_ROWS * ROW_BYTES)   /* 20480 per array */
#define STAGE_BYTES (2 * CHUNK_BYTES)          /* 40960: o + l     */
#define STAGES      4
#define SMEM_DATA   (STAGES * STAGE_BYTES)     /* 163840 bytes     */

__device__ double g_partials[NBLOCKS];
__device__ unsigned int g_count;

__device__ __forceinline__ uint32_t smem_u32(const void* p) {
    uint32_t a;
    asm("{ .reg .u64 t; cvta.to.shared.u64 t, %1; cvt.u32.u64 %0, t; }"
        : "=r"(a) : "l"(p));
    return a;
}

__device__ __forceinline__ void mbar_init(uint32_t mbar, uint32_t count) {
    asm volatile("mbarrier.init.shared.b64 [%0], %1;" :: "r"(mbar), "r"(count) : "memory");
}
__device__ __forceinline__ void mbar_expect_tx(uint32_t mbar, uint32_t bytes) {
    asm volatile("mbarrier.arrive.expect_tx.shared.b64 _, [%0], %1;"
                 :: "r"(mbar), "r"(bytes) : "memory");
}
__device__ __forceinline__ void mbar_wait_parity(uint32_t mbar, uint32_t parity) {
    uint32_t done;
    asm volatile(
        "{\n\t"
        ".reg .pred p;\n\t"
        "mbarrier.try_wait.parity.acquire.cta.shared::cta.b64 p, [%1], %2;\n\t"
        "selp.b32 %0, 1, 0, p;\n\t"
        "}" : "=r"(done) : "r"(mbar), "r"(parity) : "memory");
    if (!done) {
        asm volatile(
            "{\n\t"
            ".reg .pred P1;\n\t"
            "WL_%=:\n\t"
            "mbarrier.try_wait.parity.acquire.cta.shared::cta.b64 P1, [%0], %1, 0x989680;\n\t"
            "@P1 bra.uni WD_%=;\n\t"
            "bra.uni WL_%=;\n\t"
            "WD_%=:\n\t"
            "}" :: "r"(mbar), "r"(parity) : "memory");
    }
}
__device__ __forceinline__ void bulk_g2s(uint32_t dst, const void* src,
                                         uint32_t bytes, uint32_t mbar) {
    asm volatile(
        "cp.async.bulk.shared::cta.global.mbarrier::complete_tx::bytes [%0], [%1], %2, [%3];"
        :: "r"(dst), "l"(src), "r"(bytes), "r"(mbar) : "memory");
}

__global__ void __launch_bounds__(THREADS)
mse_tma_kernel(const float* __restrict__ o_g,
               const float* __restrict__ l_g,
               int n_rows, float* __restrict__ out) {
    extern __shared__ __align__(128) unsigned char smem[];
    __shared__ uint64_t mbar[STAGES];
    __shared__ float warp_sums[8];
    __shared__ bool is_last;

    const int tid = threadIdx.x;
    const uint32_t mbar0 = smem_u32(&mbar[0]);
    const uint32_t data0 = smem_u32(smem);

    if (tid == 0) {
        #pragma unroll
        for (int s = 0; s < STAGES; s++) mbar_init(mbar0 + s * 8, 1);
    }
    asm volatile("fence.proxy.async.shared::cta;" ::: "memory");
    __syncthreads();

    const int n_chunks = (n_rows + CHUNK_ROWS - 1) / CHUNK_ROWS;

    // Prologue: threads 0..STAGES-1 each issue one stage's loads in parallel
    // (per-stage mbarrier has a single owner, so ordering is unchanged).
    if (tid < STAGES) {
        const int it = tid;
        long long c = blockIdx.x + (long long)it * gridDim.x;
        if (c < n_chunks) {
            int rows = min(CHUNK_ROWS, (int)(n_rows - c * CHUNK_ROWS)) & ~1;
            uint32_t ob = (uint32_t)rows * ROW_BYTES;
            uint32_t mb = mbar0 + it * 8;
            uint32_t dst = data0 + it * STAGE_BYTES;
            const char* osrc = (const char*)o_g + c * (long long)CHUNK_BYTES;
            const char* lsrc = (const char*)l_g + c * (long long)CHUNK_BYTES;
            mbar_expect_tx(mb, 2 * ob);
            bulk_g2s(dst, osrc, ob, mb);
            bulk_g2s(dst + CHUNK_BYTES, lsrc, ob, mb);
        }
    }

    float acc = 0.0f;

    for (int it = 0;; it++) {
        long long c = blockIdx.x + (long long)it * gridDim.x;
        if (c >= n_chunks) break;
        const int s  = it % STAGES;
        const int ph = (it / STAGES) & 1;

        mbar_wait_parity(mbar0 + s * 8, (uint32_t)ph);

        const int rows  = min(CHUNK_ROWS, (int)(n_rows - c * CHUNK_ROWS)) & ~1;
        const int pairs = rows >> 1;

        if (tid < pairs) {
            // Two rows = 80B = 5 float4 per array. Warp LDS.128 request = 512B
            // = crossbar 4-phase floor; 80B lane stride adds no extra conflicts.
            const float4* o4 = (const float4*)(smem + s * STAGE_BYTES) + tid * 5;
            const float4* l4 = (const float4*)(smem + s * STAGE_BYTES + CHUNK_BYTES) + tid * 5;
            float4 ov0 = o4[0], ov1 = o4[1], ov2 = o4[2], ov3 = o4[3], ov4 = o4[4];
            float4 lv0 = l4[0], lv1 = l4[1], lv2 = l4[2], lv3 = l4[3], lv4 = l4[4];

            float o[20] = {ov0.x, ov0.y, ov0.z, ov0.w, ov1.x, ov1.y, ov1.z, ov1.w,
                           ov2.x, ov2.y, ov2.z, ov2.w, ov3.x, ov3.y, ov3.z, ov3.w,
                           ov4.x, ov4.y, ov4.z, ov4.w};
            float l[20] = {lv0.x, lv0.y, lv0.z, lv0.w, lv1.x, lv1.y, lv1.z, lv1.w,
                           lv2.x, lv2.y, lv2.z, lv2.w, lv3.x, lv3.y, lv3.z, lv3.w,
                           lv4.x, lv4.y, lv4.z, lv4.w};

            // COUNTS = {1,4,7,10} -> ncols = 1 + 3*cls
            int nc0 = 1 + 3 * __float2int_rn(l[0]);
            #pragma unroll
            for (int j = 0; j < 10; j++) {
                float d = o[j] - l[j];
                acc += (j < nc0) ? d * d : 0.0f;
            }
            int nc1 = 1 + 3 * __float2int_rn(l[10]);
            #pragma unroll
            for (int j = 0; j < 10; j++) {
                float d = o[10 + j] - l[10 + j];
                acc += (j < nc1) ? d * d : 0.0f;
            }
        }
        __syncthreads();  // all reads of stage s complete

        if (tid == 0) {
            int it2 = it + STAGES;
            long long c2 = blockIdx.x + (long long)it2 * gridDim.x;
            if (c2 < n_chunks) {
                int rows2 = min(CHUNK_ROWS, (int)(n_rows - c2 * CHUNK_ROWS)) & ~1;
                uint32_t ob = (uint32_t)rows2 * ROW_BYTES;
                uint32_t mb = mbar0 + s * 8;
                uint32_t dst = data0 + s * STAGE_BYTES;
                const char* osrc = (const char*)o_g + c2 * (long long)CHUNK_BYTES;
                const char* lsrc = (const char*)l_g + c2 * (long long)CHUNK_BYTES;
                mbar_expect_tx(mb, 2 * ob);
                bulk_g2s(dst, osrc, ob, mb);
                bulk_g2s(dst + CHUNK_BYTES, lsrc, ob, mb);
            }
        }
    }

    // Odd final row (n_rows odd): chunk path rounds rows down to even.
    if ((n_rows & 1) && blockIdx.x == 0 && tid == 0) {
        long long r = (long long)n_rows - 1;
        const float* orow = o_g + r * 10;
        const float* lrow = l_g + r * 10;
        int nc = 1 + 3 * __float2int_rn(lrow[0]);
        #pragma unroll
        for (int j = 0; j < 10; j++) {
            float d = orow[j] - lrow[j];
            acc += (j < nc) ? d * d : 0.0f;
        }
    }

    // Warp reduce
    #pragma unroll
    for (int off = 16; off > 0; off >>= 1)
        acc += __shfl_xor_sync(0xFFFFFFFFu, acc, off);

    int lane = tid & 31;
    int wid  = tid >> 5;
    if (lane == 0) warp_sums[wid] = acc;
    __syncthreads();

    if (wid == 0) {
        float v = (lane < 8) ? warp_sums[lane] : 0.0f;
        #pragma unroll
        for (int off = 4; off > 0; off >>= 1)
            v += __shfl_xor_sync(0xFFFFFFFFu, v, off);
        if (lane == 0) {
            g_partials[blockIdx.x] = (double)v;
            __threadfence();
            unsigned int ticket = atomicAdd(&g_count, 1u);
            is_last = (ticket == gridDim.x - 1);
        }
        __syncwarp();

        // Serial epilogue: single warp of the last block finalizes.
        if (is_last) {
            __threadfence();
            double dsum = 0.0;
            for (int i = lane; i < NBLOCKS; i += 32)
                dsum += g_partials[i];
            #pragma unroll
            for (int off = 16; off > 0; off >>= 1)
                dsum += __shfl_xor_sync(0xFFFFFFFFu, dsum, off);
            if (lane == 0) {
                out[0] = (float)(dsum / (double)n_rows);
                g_count = 0;  // reset for next graph replay
            }
        }
    }
}

extern "C" void kernel_launch(void* const* d_in, const int* in_sizes, int n_in,
                              void* d_out, int out_size) {
    const float* outputs = (const float*)d_in[0];
    const float* labels  = (const float*)d_in[1];
    float* out = (float*)d_out;

    int n_rows = in_sizes[0] / 10;

    cudaFuncSetAttribute(mse_tma_kernel,
                         cudaFuncAttributeMaxDynamicSharedMemorySize, SMEM_DATA);

    mse_tma_kernel<<<NBLOCKS, THREADS, SMEM_DATA>>>(outputs, labels, n_rows, out);
}